// round 14
// baseline (speedup 1.0000x reference)
#include <cuda_runtime.h>
#include <cuda_fp16.h>
#include <cstdint>
#include <math_constants.h>

// Problem constants
#define BB 32
#define TT 4096
#define DD 512
#define UU 512

// Scratch (allocation-free rule: __device__ globals)
__device__ float  g_qcomb[BB * UU];             // query@W1 + b1 + b2
__device__ float  g_scores[BB * TT];            // scores, then attn (in place)
__device__ __half g_w2t_h[UU * DD];             // W2 transposed [u, d], fp16
__device__ __half g_vals_h[(size_t)BB * TT * DD]; // values in fp16
#define NC_CTX 32
__device__ float g_ctxpart[NC_CTX * BB * DD];   // context partials

// ===========================================================================
// Helpers (baseline PTX only — harness compiles for sm_103 (no 'a'), so no
// tcgen05/TMEM; classic mma.sync fp16 + cp.async + ldmatrix)
// ===========================================================================
__device__ __forceinline__ uint32_t smem_u32(const void* p) {
    uint32_t a;
    asm("{ .reg .u64 t; cvta.to.shared.u64 t, %1; cvt.u32.u64 %0, t; }"
        : "=r"(a) : "l"(p));
    return a;
}
__device__ __forceinline__ void cp_async16(uint32_t dst, const void* src) {
    asm volatile("cp.async.ca.shared.global [%0], [%1], 16;"
                 :: "r"(dst), "l"(src));
}
#define CP_COMMIT() asm volatile("cp.async.commit_group;" ::: "memory")
#define CP_WAIT(n)  asm volatile("cp.async.wait_group %0;" :: "n"(n) : "memory")

__device__ __forceinline__ float tanh_fast(float x) {
    float r;
    asm("tanh.approx.f32 %0, %1;" : "=f"(r) : "f"(x));
    return r;
}
#define MMA_F16(d, a, bf) \
    asm volatile("mma.sync.aligned.m16n8k16.row.col.f32.f16.f16.f32 " \
                 "{%0,%1,%2,%3}, {%4,%5,%6,%7}, {%8,%9}, {%0,%1,%2,%3};" \
                 : "+f"((d)[0]), "+f"((d)[1]), "+f"((d)[2]), "+f"((d)[3]) \
                 : "r"((a)[0]), "r"((a)[1]), "r"((a)[2]), "r"((a)[3]), \
                   "r"((bf)[0]), "r"((bf)[1]))
#define LDMATRIX_X4(r0, r1, r2, r3, addr) \
    asm volatile("ldmatrix.sync.aligned.m8n8.x4.shared.b16 {%0,%1,%2,%3}, [%4];" \
                 : "=r"(r0), "=r"(r1), "=r"(r2), "=r"(r3) : "r"(addr))

// ===========================================================================
// Kernel P-1: convert values fp32 -> fp16
// ===========================================================================
__global__ void convert_values_kernel(const float4* __restrict__ in,
                                      __half2* __restrict__ out, int n4) {
    int i = blockIdx.x * blockDim.x + threadIdx.x;
    const int stride = gridDim.x * blockDim.x;
    for (; i < n4; i += stride) {
        float4 v = in[i];
        out[2 * i]     = __floats2half2_rn(v.x, v.y);
        out[2 * i + 1] = __floats2half2_rn(v.z, v.w);
    }
}

// ===========================================================================
// Kernel P0: transpose W2[d,u] -> W2T[u,d] in fp16
// ===========================================================================
__global__ void transpose_w2_kernel(const float* __restrict__ W2,
                                    __half* __restrict__ W2T) {
    __shared__ float tile[32][33];
    int x = blockIdx.x * 32 + threadIdx.x;  // u
    int y = blockIdx.y * 32 + threadIdx.y;  // d
#pragma unroll
    for (int j = 0; j < 32; j += 8)
        tile[threadIdx.y + j][threadIdx.x] = W2[(y + j) * UU + x];
    __syncthreads();
    x = blockIdx.y * 32 + threadIdx.x;  // d
    y = blockIdx.x * 32 + threadIdx.y;  // u
#pragma unroll
    for (int j = 0; j < 32; j += 8)
        W2T[(size_t)(y + j) * DD + x] = __float2half_rn(tile[threadIdx.x][threadIdx.y + j]);
}

// ===========================================================================
// Kernel A: qcomb[b,u] = sum_d query[b,d]*W1[d,u] + b1[u] + b2[u]
// ===========================================================================
__global__ void qproj_kernel(const float* __restrict__ query,
                             const float* __restrict__ W1,
                             const float* __restrict__ b1,
                             const float* __restrict__ b2,
                             float* __restrict__ qcomb) {
    int b = blockIdx.x;
    int u = threadIdx.x;
    __shared__ float q_s[DD];
    q_s[u] = query[b * DD + u];
    __syncthreads();
    float acc = 0.f;
#pragma unroll 8
    for (int d = 0; d < DD; d++) {
        acc += q_s[d] * W1[d * UU + u];
    }
    qcomb[b * UU + u] = acc + b1[u] + b2[u];
}

// ===========================================================================
// Kernel B: fp16 mma.sync fused scores.
// 256 threads, 8 warps = 2(m) x 4(n); warp tile 64x64; ldmatrix fragments;
// KC=128 chunks, classic 2-stage double buffer -> 8 barriers per CTA total.
// grid = (TT/128, BB)
// ===========================================================================
#define MM_THREADS 256
#define TILE_M 128
#define NTC 256          // n-chunk size
#define KC 128           // k (halfs) per staged chunk
#define KSTEPS 8         // k16 steps per chunk
#define NKCH (DD / KC)   // 4
#define NNCH (UU / NTC)  // 2
#define PH 136           // smem pitch in halfs (272B rows; conflict-free)

#define ASTG (TILE_M * PH * 2)   // 34816 B per A stage
#define BSTG (NTC * PH * 2)      // 69632 B per B stage
#define SMH_A(i) ((i) * ASTG)
#define SMH_B(i) (2 * ASTG + (i) * BSTG)
#define SMH_QC (2 * ASTG + 2 * BSTG)     // 208896
#define SMH_V  (SMH_QC + UU * 4)
#define SMH_SP (SMH_V + UU * 4)
#define SMH_TOTAL (SMH_SP + TILE_M * 4 * 4)  // 215040

__global__ __launch_bounds__(MM_THREADS, 1) void scores_mma_kernel(
    const __half* __restrict__ valsH,
    const __half* __restrict__ w2tH,
    const float* __restrict__ qcomb,
    const float* __restrict__ Vvec,
    float* __restrict__ scores)
{
    extern __shared__ __align__(16) char smem[];
    const uint32_t sbase = smem_u32(smem);
    const int tid  = threadIdx.x;
    const int wid  = tid >> 5;
    const int lane = tid & 31;
    const int b  = blockIdx.y;
    const int t0 = blockIdx.x * TILE_M;

    float* qs = (float*)(smem + SMH_QC);
    float* vs = (float*)(smem + SMH_V);
    for (int i = tid; i < UU; i += MM_THREADS) {
        qs[i] = qcomb[b * UU + i];
        vs[i] = Vvec[i];
    }

    const __half* Abase = valsH + ((size_t)b * TT + t0) * DD;
    const int warp_m = wid & 1;   // 2 x 64 rows
    const int warp_n = wid >> 1;  // 4 x 64 cols (within 256-col n-chunk)

    const uint32_t stA[2] = { sbase + SMH_A(0), sbase + SMH_A(1) };
    const uint32_t stB[2] = { sbase + SMH_B(0), sbase + SMH_B(1) };

    // ldmatrix row offsets (in halfs), invariant across chunks/ksteps
    uint32_t rowA_off[4];
#pragma unroll
    for (int mt = 0; mt < 4; mt++)
        rowA_off[mt] = (uint32_t)((warp_m * 64 + mt * 16 + (lane & 15)) * PH
                                  + (lane >> 4) * 8);
    // B, per pair p (covers nt=2p,2p+1)
    uint32_t rowB_off[4];
#pragma unroll
    for (int p = 0; p < 4; p++)
        rowB_off[p] = (uint32_t)((warp_n * 64 + p * 16 + ((lane >> 4) * 8) + (lane & 7)) * PH
                                 + ((lane >> 3) & 1) * 8);

    float score_part[8];
#pragma unroll
    for (int i = 0; i < 8; i++) score_part[i] = 0.f;

    for (int nc = 0; nc < NNCH; nc++) {
        const int n0 = nc * NTC;
        float acc[4][8][4];
#pragma unroll
        for (int mt = 0; mt < 4; mt++)
#pragma unroll
            for (int nt = 0; nt < 8; nt++)
#pragma unroll
                for (int r = 0; r < 4; r++) acc[mt][nt][r] = 0.f;

        __syncthreads();  // protect stages from previous nc's in-flight readers

        // prologue: chunk 0 -> stage 0   (A: 128x16 units, B: 256x16 units)
        {
            for (int i = tid; i < TILE_M * 16; i += MM_THREADS) {
                int r = i >> 4, q = i & 15;
                cp_async16(stA[0] + (uint32_t)(r * PH + q * 8) * 2,
                           Abase + (size_t)r * DD + q * 8);
            }
            for (int i = tid; i < NTC * 16; i += MM_THREADS) {
                int r = i >> 4, q = i & 15;
                cp_async16(stB[0] + (uint32_t)(r * PH + q * 8) * 2,
                           w2tH + (size_t)(n0 + r) * DD + q * 8);
            }
            CP_COMMIT();
        }

        for (int c = 0; c < NKCH; c++) {
            CP_WAIT(0);          // chunk c fully arrived
            __syncthreads();
            if (c + 1 < NKCH) {  // issue chunk c+1 into the other stage
                const int k0 = (c + 1) * KC;
                const int sg = (c + 1) & 1;
                for (int i = tid; i < TILE_M * 16; i += MM_THREADS) {
                    int r = i >> 4, q = i & 15;
                    cp_async16(stA[sg] + (uint32_t)(r * PH + q * 8) * 2,
                               Abase + (size_t)r * DD + k0 + q * 8);
                }
                for (int i = tid; i < NTC * 16; i += MM_THREADS) {
                    int r = i >> 4, q = i & 15;
                    cp_async16(stB[sg] + (uint32_t)(r * PH + q * 8) * 2,
                               w2tH + (size_t)(n0 + r) * DD + k0 + q * 8);
                }
                CP_COMMIT();
            }

            const uint32_t aS = stA[c & 1];
            const uint32_t bS = stB[c & 1];
#pragma unroll
            for (int kk = 0; kk < KSTEPS; kk++) {
                const uint32_t kh = (uint32_t)(kk * 16) * 2;  // byte offset of k16 step
                uint32_t afr[4][4];
#pragma unroll
                for (int mt = 0; mt < 4; mt++) {
                    LDMATRIX_X4(afr[mt][0], afr[mt][1], afr[mt][2], afr[mt][3],
                                aS + rowA_off[mt] * 2 + kh);
                }
                uint32_t bfr[4][4];
#pragma unroll
                for (int p = 0; p < 4; p++) {
                    LDMATRIX_X4(bfr[p][0], bfr[p][1], bfr[p][2], bfr[p][3],
                                bS + rowB_off[p] * 2 + kh);
                }
#pragma unroll
                for (int mt = 0; mt < 4; mt++) {
#pragma unroll
                    for (int nt = 0; nt < 8; nt++) {
                        uint32_t bq[2] = { bfr[nt >> 1][(nt & 1) * 2],
                                           bfr[nt >> 1][(nt & 1) * 2 + 1] };
                        MMA_F16(acc[mt][nt], afr[mt], bq);
                    }
                }
            }
        }

        // fused epilogue for this n-chunk: tanh + dot with V
#pragma unroll
        for (int mt = 0; mt < 4; mt++) {
#pragma unroll
            for (int nt = 0; nt < 8; nt++) {
#pragma unroll
                for (int r = 0; r < 4; r++) {
                    const int u = n0 + warp_n * 64 + nt * 8 + (lane & 3) * 2 + (r & 1);
                    const float x = acc[mt][nt][r] + qs[u];
                    score_part[mt * 2 + (r >> 1)] += tanh_fast(x) * vs[u];
                }
            }
        }
    }

    // reduce over the 4 lanes of each quad (cols), then across warp_n via smem
#pragma unroll
    for (int i = 0; i < 8; i++) {
        float v = score_part[i];
        v += __shfl_xor_sync(0xffffffffu, v, 1);
        v += __shfl_xor_sync(0xffffffffu, v, 2);
        score_part[i] = v;
    }
    float* sp = (float*)(smem + SMH_SP);  // [128 rows][4 warp_n]
    if ((lane & 3) == 0) {
#pragma unroll
        for (int mt = 0; mt < 4; mt++) {
#pragma unroll
            for (int hi = 0; hi < 2; hi++) {
                const int row = warp_m * 64 + mt * 16 + hi * 8 + (lane >> 2);
                sp[row * 4 + warp_n] = score_part[mt * 2 + hi];
            }
        }
    }
    __syncthreads();
    if (tid < TILE_M) {
        scores[b * TT + t0 + tid] =
            sp[tid * 4 + 0] + sp[tid * 4 + 1] + sp[tid * 4 + 2] + sp[tid * 4 + 3];
    }
}

// ===========================================================================
// Kernel C: softmax over T per batch, in place. grid=B, block=512.
// ===========================================================================
__global__ void softmax_kernel(float* __restrict__ scores) {
    const int b = blockIdx.x;
    float* s = scores + b * TT;
    const int tid = threadIdx.x;
    const int lane = tid & 31;
    const int warp = tid >> 5;
    __shared__ float red[16];

    float v[8];
    float mx = -CUDART_INF_F;
#pragma unroll
    for (int i = 0; i < 8; i++) {
        v[i] = s[tid + i * 512];
        mx = fmaxf(mx, v[i]);
    }
#pragma unroll
    for (int o = 16; o >= 1; o >>= 1) mx = fmaxf(mx, __shfl_xor_sync(0xffffffffu, mx, o));
    if (lane == 0) red[warp] = mx;
    __syncthreads();
    if (warp == 0) {
        float m = (lane < 16) ? red[lane] : -CUDART_INF_F;
#pragma unroll
        for (int o = 8; o >= 1; o >>= 1) m = fmaxf(m, __shfl_xor_sync(0xffffffffu, m, o));
        if (lane == 0) red[0] = m;
    }
    __syncthreads();
    const float M = red[0];
    __syncthreads();

    float sum = 0.f;
#pragma unroll
    for (int i = 0; i < 8; i++) {
        v[i] = __expf(v[i] - M);
        sum += v[i];
    }
#pragma unroll
    for (int o = 16; o >= 1; o >>= 1) sum += __shfl_xor_sync(0xffffffffu, sum, o);
    if (lane == 0) red[warp] = sum;
    __syncthreads();
    if (warp == 0) {
        float t = (lane < 16) ? red[lane] : 0.f;
#pragma unroll
        for (int o = 8; o >= 1; o >>= 1) t += __shfl_xor_sync(0xffffffffu, t, o);
        if (lane == 0) red[0] = t;
    }
    __syncthreads();
    const float inv = 1.f / red[0];
#pragma unroll
    for (int i = 0; i < 8; i++) {
        s[tid + i * 512] = v[i] * inv;
    }
}

// ===========================================================================
// Kernel D: context partials from fp16 values (half the DRAM traffic).
// grid=(32 t-chunks, B), block=128; each thread owns 4 d (2x half2).
// ===========================================================================
__global__ void context_part_kernel(const __half* __restrict__ valsH,
                                    const float* __restrict__ attn,
                                    float* __restrict__ part) {
    const int tc = blockIdx.x;   // 0..31
    const int b  = blockIdx.y;
    const int tid = threadIdx.x; // 0..127
    __shared__ float a_s[128];
    if (tid < 128) a_s[tid] = attn[b * TT + tc * 128 + tid];
    __syncthreads();
    const __half2* vb = (const __half2*)(valsH + ((size_t)b * TT + tc * 128) * DD) + tid * 2;
    float4 acc = {0.f, 0.f, 0.f, 0.f};
#pragma unroll 8
    for (int j = 0; j < 128; j++) {
        float a = a_s[j];
        __half2 h0 = vb[(size_t)j * 256];
        __half2 h1 = vb[(size_t)j * 256 + 1];
        float2 f0 = __half22float2(h0);
        float2 f1 = __half22float2(h1);
        acc.x += a * f0.x; acc.y += a * f0.y; acc.z += a * f1.x; acc.w += a * f1.y;
    }
    *(float4*)(part + ((size_t)(tc * BB + b)) * DD + tid * 4) = acc;
}

// ===========================================================================
// Kernel E: reduce partials -> output [B, D]
// ===========================================================================
__global__ void context_reduce_kernel(const float* __restrict__ part,
                                      float* __restrict__ out) {
    const int i = blockIdx.x * blockDim.x + threadIdx.x;
    float acc = 0.f;
#pragma unroll
    for (int tc = 0; tc < NC_CTX; tc++) {
        acc += part[(size_t)tc * (BB * DD) + i];
    }
    out[i] = acc;
}

// ===========================================================================
// Launch
// ===========================================================================
extern "C" void kernel_launch(void* const* d_in, const int* in_sizes, int n_in,
                              void* d_out, int out_size) {
    const float* query  = (const float*)d_in[0];  // [B, D]
    const float* values = (const float*)d_in[1];  // [B, T, D]
    const float* W1     = (const float*)d_in[2];  // [D, U]
    const float* b1     = (const float*)d_in[3];  // [U]
    const float* W2     = (const float*)d_in[4];  // [D, U]
    const float* b2     = (const float*)d_in[5];  // [U]
    const float* V      = (const float*)d_in[6];  // [U, 1]
    // d_in[7] = bv: constant over T, cancels in softmax -> unused
    float* out = (float*)d_out;                   // [B, D]

    float *qcomb, *scores, *ctxpart;
    __half *w2t_h, *vals_h;
    cudaGetSymbolAddress((void**)&qcomb, g_qcomb);
    cudaGetSymbolAddress((void**)&scores, g_scores);
    cudaGetSymbolAddress((void**)&w2t_h, g_w2t_h);
    cudaGetSymbolAddress((void**)&vals_h, g_vals_h);
    cudaGetSymbolAddress((void**)&ctxpart, g_ctxpart);

    cudaFuncSetAttribute(scores_mma_kernel,
                         cudaFuncAttributeMaxDynamicSharedMemorySize, SMH_TOTAL);

    const int n4 = (BB * TT * DD) / 4;
    convert_values_kernel<<<1184, 256>>>((const float4*)values, (__half2*)vals_h, n4);
    transpose_w2_kernel<<<dim3(16, 16), dim3(32, 8)>>>(W2, w2t_h);
    qproj_kernel<<<BB, UU>>>(query, W1, b1, b2, qcomb);

    dim3 gridS(TT / TILE_M, BB);
    scores_mma_kernel<<<gridS, MM_THREADS, SMH_TOTAL>>>(vals_h, w2t_h, qcomb, V, scores);

    softmax_kernel<<<BB, 512>>>(scores);

    dim3 gridD(NC_CTX, BB);
    context_part_kernel<<<gridD, 128>>>(vals_h, scores, ctxpart);

    context_reduce_kernel<<<(BB * DD) / 256, 256>>>(ctxpart, out);
}

// round 15
// speedup vs baseline: 1.4495x; 1.4495x over previous
#include <cuda_runtime.h>
#include <cuda_fp16.h>
#include <cstdint>
#include <math_constants.h>

// Problem constants
#define BB 32
#define TT 4096
#define DD 512
#define UU 512

// Scratch (allocation-free rule: __device__ globals)
__device__ float  g_qcomb[BB * UU];             // query@W1 + b1 + b2
__device__ float  g_scores[BB * TT];            // scores, then attn (in place)
__device__ __half g_w2t_h[UU * DD];             // W2 transposed [u, d], fp16
__device__ __half g_vals_h[(size_t)BB * TT * DD]; // values in fp16
#define NC_CTX 32
__device__ float g_ctxpart[NC_CTX * BB * DD];   // context partials

// ===========================================================================
// Helpers (baseline PTX only — harness compiles for sm_103 (no 'a'), so no
// tcgen05/TMEM; classic mma.sync fp16 + cp.async + ldmatrix)
// ===========================================================================
__device__ __forceinline__ uint32_t smem_u32(const void* p) {
    uint32_t a;
    asm("{ .reg .u64 t; cvta.to.shared.u64 t, %1; cvt.u32.u64 %0, t; }"
        : "=r"(a) : "l"(p));
    return a;
}
__device__ __forceinline__ void cp_async16(uint32_t dst, const void* src) {
    asm volatile("cp.async.ca.shared.global [%0], [%1], 16;"
                 :: "r"(dst), "l"(src));
}
#define CP_COMMIT() asm volatile("cp.async.commit_group;" ::: "memory")
#define CP_WAIT(n)  asm volatile("cp.async.wait_group %0;" :: "n"(n) : "memory")

__device__ __forceinline__ float tanh_fast(float x) {
    float r;
    asm("tanh.approx.f32 %0, %1;" : "=f"(r) : "f"(x));
    return r;
}
#define MMA_F16(d, a, bf) \
    asm volatile("mma.sync.aligned.m16n8k16.row.col.f32.f16.f16.f32 " \
                 "{%0,%1,%2,%3}, {%4,%5,%6,%7}, {%8,%9}, {%0,%1,%2,%3};" \
                 : "+f"((d)[0]), "+f"((d)[1]), "+f"((d)[2]), "+f"((d)[3]) \
                 : "r"((a)[0]), "r"((a)[1]), "r"((a)[2]), "r"((a)[3]), \
                   "r"((bf)[0]), "r"((bf)[1]))
#define LDMATRIX_X4(r0, r1, r2, r3, addr) \
    asm volatile("ldmatrix.sync.aligned.m8n8.x4.shared.b16 {%0,%1,%2,%3}, [%4];" \
                 : "=r"(r0), "=r"(r1), "=r"(r2), "=r"(r3) : "r"(addr))

// ===========================================================================
// Kernel P-1: convert values fp32 -> fp16
// ===========================================================================
__global__ void convert_values_kernel(const float4* __restrict__ in,
                                      __half2* __restrict__ out, int n4) {
    int i = blockIdx.x * blockDim.x + threadIdx.x;
    const int stride = gridDim.x * blockDim.x;
    for (; i < n4; i += stride) {
        float4 v = in[i];
        out[2 * i]     = __floats2half2_rn(v.x, v.y);
        out[2 * i + 1] = __floats2half2_rn(v.z, v.w);
    }
}

// ===========================================================================
// Kernel P0: transpose W2[d,u] -> W2T[u,d] in fp16
// ===========================================================================
__global__ void transpose_w2_kernel(const float* __restrict__ W2,
                                    __half* __restrict__ W2T) {
    __shared__ float tile[32][33];
    int x = blockIdx.x * 32 + threadIdx.x;  // u
    int y = blockIdx.y * 32 + threadIdx.y;  // d
#pragma unroll
    for (int j = 0; j < 32; j += 8)
        tile[threadIdx.y + j][threadIdx.x] = W2[(y + j) * UU + x];
    __syncthreads();
    x = blockIdx.y * 32 + threadIdx.x;  // d
    y = blockIdx.x * 32 + threadIdx.y;  // u
#pragma unroll
    for (int j = 0; j < 32; j += 8)
        W2T[(size_t)(y + j) * DD + x] = __float2half_rn(tile[threadIdx.x][threadIdx.y + j]);
}

// ===========================================================================
// Kernel A: qcomb[b,u] = sum_d query[b,d]*W1[d,u] + b1[u] + b2[u]
// ===========================================================================
__global__ void qproj_kernel(const float* __restrict__ query,
                             const float* __restrict__ W1,
                             const float* __restrict__ b1,
                             const float* __restrict__ b2,
                             float* __restrict__ qcomb) {
    int b = blockIdx.x;
    int u = threadIdx.x;
    __shared__ float q_s[DD];
    q_s[u] = query[b * DD + u];
    __syncthreads();
    float acc = 0.f;
#pragma unroll 8
    for (int d = 0; d < DD; d++) {
        acc += q_s[d] * W1[d * UU + u];
    }
    qcomb[b * UU + u] = acc + b1[u] + b2[u];
}

// ===========================================================================
// Kernel B: fp16 mma.sync fused scores (R11 config — best measured).
// 256 threads, 8 warps = 2(m) x 4(n); warp tile 64x64; ldmatrix fragments;
// 3-stage cp.async pipeline with ONE __syncthreads per 64-wide k-chunk.
// grid = (TT/128, BB)
// ===========================================================================
#define MM_THREADS 256
#define TILE_M 128
#define NTC 256          // n-chunk size
#define KC 64            // k (halfs) per staged chunk
#define KSTEPS 4         // k16 steps per chunk
#define NKCH (DD / KC)   // 8
#define NNCH (UU / NTC)  // 2
#define PH 72            // smem pitch in halfs (144B rows; conflict-free)

#define ASTG (TILE_M * PH * 2)   // 18432 B per A stage
#define BSTG (NTC * PH * 2)      // 36864 B per B stage
#define SMH_A(i) ((i) * ASTG)
#define SMH_B(i) (3 * ASTG + (i) * BSTG)
#define SMH_QC (3 * ASTG + 3 * BSTG)     // 165888
#define SMH_V  (SMH_QC + UU * 4)
#define SMH_SP (SMH_V + UU * 4)
#define SMH_TOTAL (SMH_SP + TILE_M * 4 * 4)  // 172032

__global__ __launch_bounds__(MM_THREADS, 1) void scores_mma_kernel(
    const __half* __restrict__ valsH,
    const __half* __restrict__ w2tH,
    const float* __restrict__ qcomb,
    const float* __restrict__ Vvec,
    float* __restrict__ scores)
{
    extern __shared__ __align__(16) char smem[];
    const uint32_t sbase = smem_u32(smem);
    const int tid  = threadIdx.x;
    const int wid  = tid >> 5;
    const int lane = tid & 31;
    const int b  = blockIdx.y;
    const int t0 = blockIdx.x * TILE_M;

    float* qs = (float*)(smem + SMH_QC);
    float* vs = (float*)(smem + SMH_V);
    for (int i = tid; i < UU; i += MM_THREADS) {
        qs[i] = qcomb[b * UU + i];
        vs[i] = Vvec[i];
    }

    const __half* Abase = valsH + ((size_t)b * TT + t0) * DD;
    const int warp_m = wid & 1;   // 2 x 64 rows
    const int warp_n = wid >> 1;  // 4 x 64 cols (within 256-col n-chunk)

    const uint32_t stA[3] = { sbase + SMH_A(0), sbase + SMH_A(1), sbase + SMH_A(2) };
    const uint32_t stB[3] = { sbase + SMH_B(0), sbase + SMH_B(1), sbase + SMH_B(2) };

    // ldmatrix row offsets (in halfs), invariant across chunks/ksteps
    uint32_t rowA_off[4];
#pragma unroll
    for (int mt = 0; mt < 4; mt++)
        rowA_off[mt] = (uint32_t)((warp_m * 64 + mt * 16 + (lane & 15)) * PH
                                  + (lane >> 4) * 8);
    // B, per pair p (covers nt=2p,2p+1)
    uint32_t rowB_off[4];
#pragma unroll
    for (int p = 0; p < 4; p++)
        rowB_off[p] = (uint32_t)((warp_n * 64 + p * 16 + ((lane >> 4) * 8) + (lane & 7)) * PH
                                 + ((lane >> 3) & 1) * 8);

    float score_part[8];
#pragma unroll
    for (int i = 0; i < 8; i++) score_part[i] = 0.f;

    for (int nc = 0; nc < NNCH; nc++) {
        const int n0 = nc * NTC;
        float acc[4][8][4];
#pragma unroll
        for (int mt = 0; mt < 4; mt++)
#pragma unroll
            for (int nt = 0; nt < 8; nt++)
#pragma unroll
                for (int r = 0; r < 4; r++) acc[mt][nt][r] = 0.f;

        __syncthreads();  // protect stages from previous nc's in-flight readers

        // prologue: chunks 0,1 -> stages 0,1
#pragma unroll
        for (int pc = 0; pc < 2; pc++) {
            const int k0 = pc * KC;
            for (int i = tid; i < TILE_M * 8; i += MM_THREADS) {
                int r = i >> 3, q = i & 7;
                cp_async16(stA[pc] + (uint32_t)(r * PH + q * 8) * 2,
                           Abase + (size_t)r * DD + k0 + q * 8);
            }
            for (int i = tid; i < NTC * 8; i += MM_THREADS) {
                int r = i >> 3, q = i & 7;
                cp_async16(stB[pc] + (uint32_t)(r * PH + q * 8) * 2,
                           w2tH + (size_t)(n0 + r) * DD + k0 + q * 8);
            }
            CP_COMMIT();
        }

        for (int c = 0; c < NKCH; c++) {
            if (c + 2 < NKCH) { CP_WAIT(1); } else { CP_WAIT(0); }
            __syncthreads();
            if (c + 2 < NKCH) {
                const int k0 = (c + 2) * KC;
                const int sg = (c + 2) % 3;
                for (int i = tid; i < TILE_M * 8; i += MM_THREADS) {
                    int r = i >> 3, q = i & 7;
                    cp_async16(stA[sg] + (uint32_t)(r * PH + q * 8) * 2,
                               Abase + (size_t)r * DD + k0 + q * 8);
                }
                for (int i = tid; i < NTC * 8; i += MM_THREADS) {
                    int r = i >> 3, q = i & 7;
                    cp_async16(stB[sg] + (uint32_t)(r * PH + q * 8) * 2,
                               w2tH + (size_t)(n0 + r) * DD + k0 + q * 8);
                }
                CP_COMMIT();
            }

            const uint32_t aS = stA[c % 3];
            const uint32_t bS = stB[c % 3];
#pragma unroll
            for (int kk = 0; kk < KSTEPS; kk++) {
                const uint32_t kh = (uint32_t)(kk * 16) * 2;  // byte offset of k16 step
                uint32_t afr[4][4];
#pragma unroll
                for (int mt = 0; mt < 4; mt++) {
                    LDMATRIX_X4(afr[mt][0], afr[mt][1], afr[mt][2], afr[mt][3],
                                aS + rowA_off[mt] * 2 + kh);
                }
                uint32_t bfr[4][4];
#pragma unroll
                for (int p = 0; p < 4; p++) {
                    LDMATRIX_X4(bfr[p][0], bfr[p][1], bfr[p][2], bfr[p][3],
                                bS + rowB_off[p] * 2 + kh);
                }
#pragma unroll
                for (int mt = 0; mt < 4; mt++) {
#pragma unroll
                    for (int nt = 0; nt < 8; nt++) {
                        uint32_t bq[2] = { bfr[nt >> 1][(nt & 1) * 2],
                                           bfr[nt >> 1][(nt & 1) * 2 + 1] };
                        MMA_F16(acc[mt][nt], afr[mt], bq);
                    }
                }
            }
        }

        // fused epilogue for this n-chunk: tanh + dot with V
#pragma unroll
        for (int mt = 0; mt < 4; mt++) {
#pragma unroll
            for (int nt = 0; nt < 8; nt++) {
#pragma unroll
                for (int r = 0; r < 4; r++) {
                    const int u = n0 + warp_n * 64 + nt * 8 + (lane & 3) * 2 + (r & 1);
                    const float x = acc[mt][nt][r] + qs[u];
                    score_part[mt * 2 + (r >> 1)] += tanh_fast(x) * vs[u];
                }
            }
        }
    }

    // reduce over the 4 lanes of each quad (cols), then across warp_n via smem
#pragma unroll
    for (int i = 0; i < 8; i++) {
        float v = score_part[i];
        v += __shfl_xor_sync(0xffffffffu, v, 1);
        v += __shfl_xor_sync(0xffffffffu, v, 2);
        score_part[i] = v;
    }
    float* sp = (float*)(smem + SMH_SP);  // [128 rows][4 warp_n]
    if ((lane & 3) == 0) {
#pragma unroll
        for (int mt = 0; mt < 4; mt++) {
#pragma unroll
            for (int hi = 0; hi < 2; hi++) {
                const int row = warp_m * 64 + mt * 16 + hi * 8 + (lane >> 2);
                sp[row * 4 + warp_n] = score_part[mt * 2 + hi];
            }
        }
    }
    __syncthreads();
    if (tid < TILE_M) {
        scores[b * TT + t0 + tid] =
            sp[tid * 4 + 0] + sp[tid * 4 + 1] + sp[tid * 4 + 2] + sp[tid * 4 + 3];
    }
}

// ===========================================================================
// Kernel C: softmax over T per batch, in place. grid=B, block=512.
// ===========================================================================
__global__ void softmax_kernel(float* __restrict__ scores) {
    const int b = blockIdx.x;
    float* s = scores + b * TT;
    const int tid = threadIdx.x;
    const int lane = tid & 31;
    const int warp = tid >> 5;
    __shared__ float red[16];

    float v[8];
    float mx = -CUDART_INF_F;
#pragma unroll
    for (int i = 0; i < 8; i++) {
        v[i] = s[tid + i * 512];
        mx = fmaxf(mx, v[i]);
    }
#pragma unroll
    for (int o = 16; o >= 1; o >>= 1) mx = fmaxf(mx, __shfl_xor_sync(0xffffffffu, mx, o));
    if (lane == 0) red[warp] = mx;
    __syncthreads();
    if (warp == 0) {
        float m = (lane < 16) ? red[lane] : -CUDART_INF_F;
#pragma unroll
        for (int o = 8; o >= 1; o >>= 1) m = fmaxf(m, __shfl_xor_sync(0xffffffffu, m, o));
        if (lane == 0) red[0] = m;
    }
    __syncthreads();
    const float M = red[0];
    __syncthreads();

    float sum = 0.f;
#pragma unroll
    for (int i = 0; i < 8; i++) {
        v[i] = __expf(v[i] - M);
        sum += v[i];
    }
#pragma unroll
    for (int o = 16; o >= 1; o >>= 1) sum += __shfl_xor_sync(0xffffffffu, sum, o);
    if (lane == 0) red[warp] = sum;
    __syncthreads();
    if (warp == 0) {
        float t = (lane < 16) ? red[lane] : 0.f;
#pragma unroll
        for (int o = 8; o >= 1; o >>= 1) t += __shfl_xor_sync(0xffffffffu, t, o);
        if (lane == 0) red[0] = t;
    }
    __syncthreads();
    const float inv = 1.f / red[0];
#pragma unroll
    for (int i = 0; i < 8; i++) {
        s[tid + i * 512] = v[i] * inv;
    }
}

// ===========================================================================
// Kernel D: context partials from fp16 values (half the DRAM traffic).
// grid=(32 t-chunks, B), block=128; each thread owns 4 d (2x half2).
// ===========================================================================
__global__ void context_part_kernel(const __half* __restrict__ valsH,
                                    const float* __restrict__ attn,
                                    float* __restrict__ part) {
    const int tc = blockIdx.x;   // 0..31
    const int b  = blockIdx.y;
    const int tid = threadIdx.x; // 0..127
    __shared__ float a_s[128];
    if (tid < 128) a_s[tid] = attn[b * TT + tc * 128 + tid];
    __syncthreads();
    const __half2* vb = (const __half2*)(valsH + ((size_t)b * TT + tc * 128) * DD) + tid * 2;
    float4 acc = {0.f, 0.f, 0.f, 0.f};
#pragma unroll 8
    for (int j = 0; j < 128; j++) {
        float a = a_s[j];
        __half2 h0 = vb[(size_t)j * 256];
        __half2 h1 = vb[(size_t)j * 256 + 1];
        float2 f0 = __half22float2(h0);
        float2 f1 = __half22float2(h1);
        acc.x += a * f0.x; acc.y += a * f0.y; acc.z += a * f1.x; acc.w += a * f1.y;
    }
    *(float4*)(part + ((size_t)(tc * BB + b)) * DD + tid * 4) = acc;
}

// ===========================================================================
// Kernel E: reduce partials -> output [B, D]
// ===========================================================================
__global__ void context_reduce_kernel(const float* __restrict__ part,
                                      float* __restrict__ out) {
    const int i = blockIdx.x * blockDim.x + threadIdx.x;
    float acc = 0.f;
#pragma unroll
    for (int tc = 0; tc < NC_CTX; tc++) {
        acc += part[(size_t)tc * (BB * DD) + i];
    }
    out[i] = acc;
}

// ===========================================================================
// Launch
// ===========================================================================
extern "C" void kernel_launch(void* const* d_in, const int* in_sizes, int n_in,
                              void* d_out, int out_size) {
    const float* query  = (const float*)d_in[0];  // [B, D]
    const float* values = (const float*)d_in[1];  // [B, T, D]
    const float* W1     = (const float*)d_in[2];  // [D, U]
    const float* b1     = (const float*)d_in[3];  // [U]
    const float* W2     = (const float*)d_in[4];  // [D, U]
    const float* b2     = (const float*)d_in[5];  // [U]
    const float* V      = (const float*)d_in[6];  // [U, 1]
    // d_in[7] = bv: constant over T, cancels in softmax -> unused
    float* out = (float*)d_out;                   // [B, D]

    float *qcomb, *scores, *ctxpart;
    __half *w2t_h, *vals_h;
    cudaGetSymbolAddress((void**)&qcomb, g_qcomb);
    cudaGetSymbolAddress((void**)&scores, g_scores);
    cudaGetSymbolAddress((void**)&w2t_h, g_w2t_h);
    cudaGetSymbolAddress((void**)&vals_h, g_vals_h);
    cudaGetSymbolAddress((void**)&ctxpart, g_ctxpart);

    cudaFuncSetAttribute(scores_mma_kernel,
                         cudaFuncAttributeMaxDynamicSharedMemorySize, SMH_TOTAL);

    const int n4 = (BB * TT * DD) / 4;
    convert_values_kernel<<<1184, 256>>>((const float4*)values, (__half2*)vals_h, n4);
    transpose_w2_kernel<<<dim3(16, 16), dim3(32, 8)>>>(W2, w2t_h);
    qproj_kernel<<<BB, UU>>>(query, W1, b1, b2, qcomb);

    dim3 gridS(TT / TILE_M, BB);
    scores_mma_kernel<<<gridS, MM_THREADS, SMH_TOTAL>>>(vals_h, w2t_h, qcomb, V, scores);

    softmax_kernel<<<BB, 512>>>(scores);

    dim3 gridD(NC_CTX, BB);
    context_part_kernel<<<gridD, 128>>>(vals_h, scores, ctxpart);

    context_reduce_kernel<<<(BB * DD) / 256, 256>>>(ctxpart, out);
}